// round 6
// baseline (speedup 1.0000x reference)
#include <cuda_runtime.h>
#include <cuda_bf16.h>
#include <math.h>

#define NN_ 50000
#define GG_ 2500
#define PGRID 4096
#define INV_SQMZ 0.04419417382415922f

typedef unsigned long long ull;

// ---------------- device scratch ----------------
__device__ float g_sinv[(size_t)NN_ * 384];   // per-node invariant norms
__device__ float g_scov[(size_t)GG_ * 1152];  // focused-node cov vectors (with /SQ_MZ)
__device__ float g_fl[NN_];                   // focus logits
__device__ float g_el[(size_t)NN_ * 4];       // element logits
__device__ float g_Y[9 * PGRID];              // SH basis on Fibonacci grid, [j][p]
__device__ float g_lp12[GG_];                 // lp_focus + lp_element

__device__ __forceinline__ float wsum(float v) {
#pragma unroll
    for (int s = 16; s > 0; s >>= 1) v += __shfl_xor_sync(0xffffffffu, v, s);
    return v;
}

__device__ __forceinline__ ull pk2(float lo, float hi) {
    ull r;
    asm("mov.b64 %0, {%1, %2};" : "=l"(r) : "f"(lo), "f"(hi));
    return r;
}
__device__ __forceinline__ void upk2(ull v, float& lo, float& hi) {
    asm("mov.b64 {%0, %1}, %2;" : "=f"(lo), "=f"(hi) : "l"(v));
}
__device__ __forceinline__ void fma2_(ull& d, ull a, ull b) {
    asm("fma.rn.f32x2 %0, %1, %2, %0;" : "+l"(d) : "l"(a), "l"(b));
}

// ---------------- K0: build Y_GRID ----------------
__global__ void k0_ygrid() {
    int i = blockIdx.x * blockDim.x + threadIdx.x;
    if (i >= PGRID) return;
    double ph = 3.14159265358979323846 * (3.0 - sqrt(5.0)) * (double)i;
    double z  = 1.0 - 2.0 * ((double)i + 0.5) / (double)PGRID;
    double rr = 1.0 - z * z; if (rr < 0.0) rr = 0.0;
    double r  = sqrt(rr);
    float x  = (float)(r * cos(ph));
    float y  = (float)(r * sin(ph));
    float zf = (float)z;
    g_Y[0 * PGRID + i] = 0.28209479177387814f;
    g_Y[1 * PGRID + i] = 0.4886025119029199f * y;
    g_Y[2 * PGRID + i] = 0.4886025119029199f * zf;
    g_Y[3 * PGRID + i] = 0.4886025119029199f * x;
    g_Y[4 * PGRID + i] = 1.0925484305920792f * x * y;
    g_Y[5 * PGRID + i] = 1.0925484305920792f * y * zf;
    g_Y[6 * PGRID + i] = 0.31539156525252005f * (3.f * zf * zf - 1.f);
    g_Y[7 * PGRID + i] = 1.0925484305920792f * x * zf;
    g_Y[8 * PGRID + i] = 0.5462742152960396f * (x * x - y * y);
}

// ---------------- K1 (L=1,2): per-group cov GEMM + norms ----------------
// 320 threads: cq = tid&63 -> cols {2cq, 2cq+1}; nq = tid>>6 -> nodes 4nq..4nq+3.
// FFMA2 lanes pair nodes; W pre-duplicated in smem; small tile -> high occupancy.
template <int L>
__global__ void __launch_bounds__(320, 2) k1_cov(
    const float* __restrict__ s_inter, const float* __restrict__ bag,
    const int* __restrict__ ptr, const int* __restrict__ focus,
    const float* __restrict__ W_bag)
{
    constexpr int OL  = (L == 1) ? 3 : 5;
    constexpr int OFF = (L == 1) ? 128 : 512;

    __shared__ __align__(16) float sW2[32 * 256];       // dup pairs [kk][col dup]
    __shared__ __align__(16) float sX[32 * OL * 20];    // [kk*OL+m][n]

    const int g   = blockIdx.x;
    const int tid = threadIdx.x;
    const int cq  = tid & 63;
    const int nq  = tid >> 6;
    const int n0  = ptr[g];
    const float b0 = bag[g * 4 + 0], b1 = bag[g * 4 + 1];
    const float b2 = bag[g * 4 + 2], b3 = bag[g * 4 + 3];
    const float* Wl = W_bag + (size_t)L * 65536;

    ull acc[2][2][OL];
#pragma unroll
    for (int cc = 0; cc < 2; cc++)
#pragma unroll
        for (int np = 0; np < 2; np++)
#pragma unroll
            for (int m = 0; m < OL; m++) acc[cc][np][m] = 0ull;

    for (int ic = 0; ic < 128; ic += 32) {
        // build dup'd W_eff chunk
        for (int e = tid; e < 1024; e += 320) {
            const int kk = e >> 5, c4 = (e & 31) << 2;
            const float* wp = Wl + (size_t)(ic + kk) * 512 + c4;
            const float4 w0 = *reinterpret_cast<const float4*>(wp);
            const float4 w1 = *reinterpret_cast<const float4*>(wp + 128);
            const float4 w2 = *reinterpret_cast<const float4*>(wp + 256);
            const float4 w3 = *reinterpret_cast<const float4*>(wp + 384);
            float4 r;
            r.x = fmaf(b0, w0.x, fmaf(b1, w1.x, fmaf(b2, w2.x, b3 * w3.x)));
            r.y = fmaf(b0, w0.y, fmaf(b1, w1.y, fmaf(b2, w2.y, b3 * w3.y)));
            r.z = fmaf(b0, w0.z, fmaf(b1, w1.z, fmaf(b2, w2.z, b3 * w3.z)));
            r.w = fmaf(b0, w0.w, fmaf(b1, w1.w, fmaf(b2, w2.w, b3 * w3.w)));
            *reinterpret_cast<float4*>(sW2 + kk * 256 + c4 * 2)     =
                make_float4(r.x, r.x, r.y, r.y);
            *reinterpret_cast<float4*>(sW2 + kk * 256 + c4 * 2 + 4) =
                make_float4(r.z, r.z, r.w, r.w);
        }
        // stage X chunk: sX[j*20 + nl], j = kk*OL + m
        for (int e = tid; e < 20 * 32 * OL; e += 320) {
            const int nl = e / (32 * OL);
            const int j  = e - nl * (32 * OL);
            sX[j * 20 + nl] = s_inter[(size_t)(n0 + nl) * 1152 + OFF + ic * OL + j];
        }
        __syncthreads();

        for (int kk = 0; kk < 32; kk++) {
            const ulonglong2 wv = *reinterpret_cast<const ulonglong2*>(
                sW2 + kk * 256 + cq * 4);
#pragma unroll
            for (int m = 0; m < OL; m++) {
                const ulonglong2 xv = *reinterpret_cast<const ulonglong2*>(
                    sX + (kk * OL + m) * 20 + nq * 4);
                fma2_(acc[0][0][m], wv.x, xv.x);
                fma2_(acc[0][1][m], wv.x, xv.y);
                fma2_(acc[1][0][m], wv.y, xv.x);
                fma2_(acc[1][1][m], wv.y, xv.y);
            }
        }
        __syncthreads();
    }

    const int foc = focus[g];
#pragma unroll
    for (int cc = 0; cc < 2; cc++) {
        const int col = cq * 2 + cc;
#pragma unroll
        for (int np = 0; np < 2; np++) {
            const int nloc = nq * 4 + np * 2;
            float s0 = 1e-12f, s1 = 1e-12f;
            float lo[OL], hi[OL];
#pragma unroll
            for (int m = 0; m < OL; m++) {
                float l, h;
                upk2(acc[cc][np][m], l, h);
                l *= INV_SQMZ; h *= INV_SQMZ;
                s0 = fmaf(l, l, s0); s1 = fmaf(h, h, s1);
                lo[m] = l; hi[m] = h;
            }
            const int na = n0 + nloc;
            g_sinv[(size_t)na * 384 + L * 128 + col]       = sqrtf(s0);
            g_sinv[(size_t)(na + 1) * 384 + L * 128 + col] = sqrtf(s1);
            if (nloc == foc) {
#pragma unroll
                for (int m = 0; m < OL; m++)
                    g_scov[(size_t)g * 1152 + OFF + col * OL + m] = lo[m];
            }
            if (nloc + 1 == foc) {
#pragma unroll
                for (int m = 0; m < OL; m++)
                    g_scov[(size_t)g * 1152 + OFF + col * OL + m] = hi[m];
            }
        }
    }
}

// ---------------- K1 (L=0): cols paired, X pre-duplicated ----------------
__global__ void __launch_bounds__(160, 4) k1_cov0(
    const float* __restrict__ s_inter, const float* __restrict__ bag,
    const int* __restrict__ ptr, const int* __restrict__ focus,
    const float* __restrict__ W_bag)
{
    __shared__ __align__(16) float sW[32 * 128];   // normal W_eff
    __shared__ __align__(16) float sX2[32 * 40];   // dup'd x: [kk][n dup]

    const int g   = blockIdx.x;
    const int tid = threadIdx.x;
    const int cq  = tid & 31;
    const int nq  = tid >> 5;
    const int n0  = ptr[g];
    const float b0 = bag[g * 4 + 0], b1 = bag[g * 4 + 1];
    const float b2 = bag[g * 4 + 2], b3 = bag[g * 4 + 3];
    const float* Wl = W_bag;

    ull acc[2][4];
#pragma unroll
    for (int cp = 0; cp < 2; cp++)
#pragma unroll
        for (int nl = 0; nl < 4; nl++) acc[cp][nl] = 0ull;

    for (int ic = 0; ic < 128; ic += 32) {
        for (int e = tid; e < 1024; e += 160) {
            const int kk = e >> 5, c4 = (e & 31) << 2;
            const float* wp = Wl + (size_t)(ic + kk) * 512 + c4;
            const float4 w0 = *reinterpret_cast<const float4*>(wp);
            const float4 w1 = *reinterpret_cast<const float4*>(wp + 128);
            const float4 w2 = *reinterpret_cast<const float4*>(wp + 256);
            const float4 w3 = *reinterpret_cast<const float4*>(wp + 384);
            float4 r;
            r.x = fmaf(b0, w0.x, fmaf(b1, w1.x, fmaf(b2, w2.x, b3 * w3.x)));
            r.y = fmaf(b0, w0.y, fmaf(b1, w1.y, fmaf(b2, w2.y, b3 * w3.y)));
            r.z = fmaf(b0, w0.z, fmaf(b1, w1.z, fmaf(b2, w2.z, b3 * w3.z)));
            r.w = fmaf(b0, w0.w, fmaf(b1, w1.w, fmaf(b2, w2.w, b3 * w3.w)));
            *reinterpret_cast<float4*>(sW + kk * 128 + c4) = r;
        }
        for (int e = tid; e < 640; e += 160) {
            const int nl = e >> 5, kk = e & 31;
            const float v = s_inter[(size_t)(n0 + nl) * 1152 + ic + kk];
            *reinterpret_cast<float2*>(sX2 + kk * 40 + nl * 2) = make_float2(v, v);
        }
        __syncthreads();

        for (int kk = 0; kk < 32; kk++) {
            const ulonglong2 wv = *reinterpret_cast<const ulonglong2*>(sW + kk * 128 + cq * 4);
            const ulonglong2 xa = *reinterpret_cast<const ulonglong2*>(sX2 + kk * 40 + nq * 8);
            const ulonglong2 xb = *reinterpret_cast<const ulonglong2*>(sX2 + kk * 40 + nq * 8 + 4);
            fma2_(acc[0][0], wv.x, xa.x); fma2_(acc[1][0], wv.y, xa.x);
            fma2_(acc[0][1], wv.x, xa.y); fma2_(acc[1][1], wv.y, xa.y);
            fma2_(acc[0][2], wv.x, xb.x); fma2_(acc[1][2], wv.y, xb.x);
            fma2_(acc[0][3], wv.x, xb.y); fma2_(acc[1][3], wv.y, xb.y);
        }
        __syncthreads();
    }

    const int foc = focus[g];
#pragma unroll
    for (int cp = 0; cp < 2; cp++) {
        const int col0 = cq * 4 + cp * 2;
#pragma unroll
        for (int nl = 0; nl < 4; nl++) {
            float c0, c1;
            upk2(acc[cp][nl], c0, c1);
            c0 *= INV_SQMZ; c1 *= INV_SQMZ;
            const int n = n0 + nq * 4 + nl;
            g_sinv[(size_t)n * 384 + col0]     = sqrtf(fmaf(c0, c0, 1e-12f));
            g_sinv[(size_t)n * 384 + col0 + 1] = sqrtf(fmaf(c1, c1, 1e-12f));
            if (nq * 4 + nl == foc) {
                g_scov[(size_t)g * 1152 + col0]     = c0;
                g_scov[(size_t)g * 1152 + col0 + 1] = c1;
            }
        }
    }
}

// ---------------- K2: fused focus + element MLPs ----------------
__global__ void __launch_bounds__(128, 4) k2_mlp(
    const float* __restrict__ gW1f, const float* __restrict__ gb1f,
    const float* __restrict__ gW2f, const float* __restrict__ gb2f,
    const float* __restrict__ gW1e, const float* __restrict__ gb1e,
    const float* __restrict__ gW2e, const float* __restrict__ gb2e)
{
    __shared__ __align__(16) float sS[384 * 32];     // [k][nn]
    const int tid = threadIdx.x;
    const int nb  = blockIdx.x * 32;
    for (int e = tid; e < 96 * 32; e += 128) {
        const int kq = e >> 5, nn = e & 31;
        const int nglob = nb + nn;
        float4 v = make_float4(0.f, 0.f, 0.f, 0.f);
        if (nglob < NN_)
            v = *reinterpret_cast<const float4*>(g_sinv + (size_t)nglob * 384 + kq * 4);
        sS[(kq * 4 + 0) * 32 + nn] = v.x;
        sS[(kq * 4 + 1) * 32 + nn] = v.y;
        sS[(kq * 4 + 2) * 32 + nn] = v.z;
        sS[(kq * 4 + 3) * 32 + nn] = v.w;
    }
    __syncthreads();

    const float bf = gb1f[tid], be = gb1e[tid];
    ull acc2f[16], acc2e[16];
#pragma unroll
    for (int p = 0; p < 16; p++) { acc2f[p] = pk2(bf, bf); acc2e[p] = pk2(be, be); }

    for (int k0 = 0; k0 < 384; k0 += 4) {
        float wf[4], we[4];
#pragma unroll
        for (int q = 0; q < 4; q++) {
            wf[q] = gW1f[(k0 + q) * 128 + tid];
            we[q] = gW1e[(k0 + q) * 128 + tid];
        }
#pragma unroll
        for (int q = 0; q < 4; q++) {
            const ull wf2 = pk2(wf[q], wf[q]);
            const ull we2 = pk2(we[q], we[q]);
            const ulonglong2* x2 = reinterpret_cast<const ulonglong2*>(sS + (k0 + q) * 32);
#pragma unroll
            for (int p8 = 0; p8 < 8; p8++) {
                const ulonglong2 xx = x2[p8];
                fma2_(acc2f[p8 * 2 + 0], wf2, xx.x);
                fma2_(acc2f[p8 * 2 + 1], wf2, xx.y);
                fma2_(acc2e[p8 * 2 + 0], we2, xx.x);
                fma2_(acc2e[p8 * 2 + 1], we2, xx.y);
            }
        }
    }

    float accf[32], acce[32];
#pragma unroll
    for (int p = 0; p < 16; p++) {
        upk2(acc2f[p], accf[2 * p], accf[2 * p + 1]);
        upk2(acc2e[p], acce[2 * p], acce[2 * p + 1]);
    }

    const float w2f = gW2f[tid];
    float w2e[4];
#pragma unroll
    for (int z = 0; z < 4; z++) w2e[z] = gW2e[tid * 4 + z];
    const int lane = tid & 31, wid = tid >> 5;
    __syncthreads();
    float* sR = sS;
    for (int nn = 0; nn < 32; nn++) {
        const float hf = fmaxf(accf[nn], 0.f);
        const float he = fmaxf(acce[nn], 0.f);
        float v0 = hf * w2f, v1 = he * w2e[0], v2 = he * w2e[1],
              v3 = he * w2e[2], v4 = he * w2e[3];
#pragma unroll
        for (int s = 16; s > 0; s >>= 1) {
            v0 += __shfl_down_sync(0xffffffffu, v0, s);
            v1 += __shfl_down_sync(0xffffffffu, v1, s);
            v2 += __shfl_down_sync(0xffffffffu, v2, s);
            v3 += __shfl_down_sync(0xffffffffu, v3, s);
            v4 += __shfl_down_sync(0xffffffffu, v4, s);
        }
        if (lane == 0) {
            const int base = (wid * 32 + nn) * 5;
            sR[base + 0] = v0; sR[base + 1] = v1; sR[base + 2] = v2;
            sR[base + 3] = v3; sR[base + 4] = v4;
        }
    }
    __syncthreads();
    if (tid < 32) {
        const int nglob = nb + tid;
        if (nglob < NN_) {
            float f = gb2f[0];
#pragma unroll
            for (int w = 0; w < 4; w++) f += sR[(w * 32 + tid) * 5 + 0];
            g_fl[nglob] = f;
#pragma unroll
            for (int z = 0; z < 4; z++) {
                float e = gb2e[z];
#pragma unroll
                for (int w = 0; w < 4; w++) e += sR[(w * 32 + tid) * 5 + 1 + z];
                g_el[(size_t)nglob * 4 + z] = e;
            }
        }
    }
}

// ---------------- K3: group softmaxes / entropies ----------------
__global__ void __launch_bounds__(128) k3_group(
    const float* __restrict__ bag, const int* __restrict__ ptr,
    const int* __restrict__ focus, const int* __restrict__ element,
    float* __restrict__ out)
{
    const int g = blockIdx.x * 4 + (threadIdx.x >> 5);
    const int lane = threadIdx.x & 31;
    if (g >= GG_) return;
    const int n0 = ptr[g];
    const int cnt = ptr[g + 1] - n0;
    const int foc = focus[g];
    const int zel = element[g];
    const bool valid = lane < cnt;
    const int n = n0 + lane;
    float f = valid ? g_fl[n] : -3.0e38f;
    float mx = f;
#pragma unroll
    for (int s = 16; s > 0; s >>= 1) mx = fmaxf(mx, __shfl_xor_sync(0xffffffffu, mx, s));
    const float ex = valid ? expf(f - mx) : 0.f;
    const float S  = wsum(ex);
    const float fp = ex / S;
    const float hfocus = wsum(valid ? -fp * logf(fp + 1e-20f) : 0.f);
    float hel = 0.f, pzel = 0.f;
    if (valid) {
        float lz[4];
        float m4 = -3.0e38f;
#pragma unroll
        for (int z = 0; z < 4; z++) {
            float v = g_el[(size_t)n * 4 + z];
            v = (bag[g * 4 + z] > 0.f) ? v : -1e9f;
            lz[z] = v; m4 = fmaxf(m4, v);
        }
        float s4 = 0.f;
#pragma unroll
        for (int z = 0; z < 4; z++) { lz[z] = expf(lz[z] - m4); s4 += lz[z]; }
#pragma unroll
        for (int z = 0; z < 4; z++) {
            lz[z] /= s4;
            hel -= lz[z] * logf(fmaxf(lz[z], 1e-20f));
        }
        pzel = lz[zel];
    }
    const float hef = wsum(fp * hel);
    const float lp = wsum((valid && lane == foc)
                          ? (logf(fp + 1e-20f) + logf(pzel + 1e-20f)) : 0.f);
    if (lane == 0) { g_lp12[g] = lp; out[2 * g + 1] = hfocus + hef; }
}

// ---------------- K5: distance MLP/GMM + cond + orientation logZ ----------------
__global__ void __launch_bounds__(128) k5_final(
    const int* __restrict__ ptr, const int* __restrict__ focus,
    const int* __restrict__ element, const float* __restrict__ distance,
    const float* __restrict__ orientation, const float* __restrict__ W_mix,
    const float* __restrict__ W1d, const float* __restrict__ b1d,
    const float* __restrict__ W2d, const float* __restrict__ b2d,
    const float* __restrict__ d_log_stds, float* __restrict__ out)
{
    const int tid = threadIdx.x, lane = tid & 31, wq = tid >> 5;
    const int gbase = blockIdx.x * 4;
    __shared__ float sSI[4][384];
    __shared__ int   sGI[4], sEl[4];
    __shared__ float sRed[4][4][6];
    if (tid < 4) {
        const int g = gbase + tid;
        sGI[tid] = (g < GG_) ? (ptr[g] + focus[g]) : 0;
        sEl[tid] = (g < GG_) ? element[g] : 0;
    }
    __syncthreads();
#pragma unroll
    for (int q = 0; q < 4; q++)
        for (int k = tid; k < 384; k += 128)
            sSI[q][k] = g_sinv[(size_t)sGI[q] * 384 + k];
    __syncthreads();

    float acc[4];
    const float b1 = b1d[tid];
#pragma unroll
    for (int q = 0; q < 4; q++) acc[q] = b1;
    for (int k = 0; k < 384; k++) {
        const float w = W1d[k * 128 + tid];
#pragma unroll
        for (int q = 0; q < 4; q++) acc[q] = fmaf(w, sSI[q][k], acc[q]);
    }
#pragma unroll
    for (int q = 0; q < 4; q++) acc[q] += W1d[(384 + sEl[q]) * 128 + tid];

    float w2[6];
#pragma unroll
    for (int j = 0; j < 6; j++) w2[j] = W2d[tid * 6 + j];
#pragma unroll
    for (int q = 0; q < 4; q++) {
        const float h = fmaxf(acc[q], 0.f);
        float v[6];
#pragma unroll
        for (int j = 0; j < 6; j++) v[j] = h * w2[j];
#pragma unroll
        for (int s = 16; s > 0; s >>= 1)
#pragma unroll
            for (int j = 0; j < 6; j++) v[j] += __shfl_down_sync(0xffffffffu, v[j], s);
        if (lane == 0)
#pragma unroll
            for (int j = 0; j < 6; j++) sRed[wq][q][j] = v[j];
    }
    __syncthreads();

    const int g = gbase + wq;
    if (g >= GG_) return;
    float hj[6];
#pragma unroll
    for (int j = 0; j < 6; j++)
        hj[j] = sRed[0][wq][j] + sRed[1][wq][j] + sRed[2][wq][j] + sRed[3][wq][j] + b2d[j];

    const float d = distance[g];
    float lm = fmaxf(hj[0], fmaxf(hj[1], hj[2]));
    float se = expf(hj[0] - lm) + expf(hj[1] - lm) + expf(hj[2] - lm);
    const float lse = lm + logf(se);
    float aj[3];
#pragma unroll
    for (int j = 0; j < 3; j++) {
        const float mean = tanhf(hj[3 + j]) * 0.45f + 1.35f;
        const float std  = fmaxf(expf(d_log_stds[j]), 1e-6f);
        const float t = (d - mean) / std;
        aj[j] = (hj[j] - lse) - 0.5f * t * t - logf(std) - 0.91893853320467274f;
    }
    float am = fmaxf(aj[0], fmaxf(aj[1], aj[2]));
    const float lp_dist = am + logf(expf(aj[0] - am) + expf(aj[1] - am) + expf(aj[2] - am));

    float bess[8];
#pragma unroll
    for (int k = 0; k < 8; k++)
        bess[k] = 1.0540925533894598f * sinf((float)(k + 1) * 3.14159265358979f * d / 1.8f) / d;

    const int zel = sEl[wq];
    float cond[9];
#pragma unroll
    for (int j = 0; j < 9; j++) cond[j] = 0.f;
    const float* scov = g_scov + (size_t)g * 1152;
#pragma unroll
    for (int ib = 0; ib < 4; ib++) {
        const int i = lane + ib * 32;
        {
            float tw = 0.f;
#pragma unroll
            for (int k = 0; k < 8; k++)
                tw = fmaf(bess[k], W_mix[k * 1536 + 0 * 512 + i * 4 + zel], tw);
            tw *= 0.3535533905932738f;
            cond[0] = fmaf(scov[i], tw, cond[0]);
        }
        {
            float tw = 0.f;
#pragma unroll
            for (int k = 0; k < 8; k++)
                tw = fmaf(bess[k], W_mix[k * 1536 + 1 * 512 + i * 4 + zel], tw);
            tw *= 0.3535533905932738f;
#pragma unroll
            for (int m = 0; m < 3; m++)
                cond[1 + m] = fmaf(scov[128 + i * 3 + m], tw, cond[1 + m]);
        }
        {
            float tw = 0.f;
#pragma unroll
            for (int k = 0; k < 8; k++)
                tw = fmaf(bess[k], W_mix[k * 1536 + 2 * 512 + i * 4 + zel], tw);
            tw *= 0.3535533905932738f;
#pragma unroll
            for (int m = 0; m < 5; m++)
                cond[4 + m] = fmaf(scov[512 + i * 5 + m], tw, cond[4 + m]);
        }
    }
#pragma unroll
    for (int j = 0; j < 9; j++) cond[j] = wsum(cond[j]) * INV_SQMZ;

    float m_run = -3.0e38f, s_run = 0.f;
    for (int t = 0; t < 128; t++) {
        const int p = lane + 32 * t;
        float f = 0.f;
#pragma unroll
        for (int j = 0; j < 9; j++) f = fmaf(cond[j], g_Y[j * PGRID + p], f);
        f *= 10.0f;
        const float nm = fmaxf(m_run, f);
        s_run = s_run * __expf(m_run - nm) + __expf(f - nm);
        m_run = nm;
    }
#pragma unroll
    for (int s = 16; s > 0; s >>= 1) {
        const float om = __shfl_xor_sync(0xffffffffu, m_run, s);
        const float os = __shfl_xor_sync(0xffffffffu, s_run, s);
        const float nm = fmaxf(m_run, om);
        s_run = s_run * __expf(m_run - nm) + os * __expf(om - nm);
        m_run = nm;
    }
    const float logZ = m_run + logf(s_run) - 8.317766166719343f + 2.5310242469692907f;

    if (lane == 0) {
        float ox = orientation[g * 3 + 0], oy = orientation[g * 3 + 1],
              oz = orientation[g * 3 + 2];
        const float inv = rsqrtf(ox * ox + oy * oy + oz * oz);
        ox *= inv; oy *= inv; oz *= inv;
        float sh[9];
        sh[0] = 0.28209479177387814f;
        sh[1] = 0.4886025119029199f * oy;
        sh[2] = 0.4886025119029199f * oz;
        sh[3] = 0.4886025119029199f * ox;
        sh[4] = 1.0925484305920792f * ox * oy;
        sh[5] = 1.0925484305920792f * oy * oz;
        sh[6] = 0.31539156525252005f * (3.f * oz * oz - 1.f);
        sh[7] = 1.0925484305920792f * ox * oz;
        sh[8] = 0.5462742152960396f * (ox * ox - oy * oy);
        float f_x = 0.f;
#pragma unroll
        for (int j = 0; j < 9; j++) f_x = fmaf(cond[j], sh[j], f_x);
        const float lp_ori = 10.0f * f_x - logZ;
        out[2 * g] = g_lp12[g] + lp_dist + lp_ori;
    }
}

// ---------------- launch ----------------
extern "C" void kernel_launch(void* const* d_in, const int* in_sizes, int n_in,
                              void* d_out, int out_size) {
    const float* s_inter     = (const float*)d_in[0];
    const float* bag         = (const float*)d_in[1];
    const int*   ptr         = (const int*)  d_in[3];
    const int*   focus       = (const int*)  d_in[4];
    const int*   element     = (const int*)  d_in[5];
    const float* distance    = (const float*)d_in[6];
    const float* orientation = (const float*)d_in[7];
    const float* W_bag       = (const float*)d_in[8];
    const float* d_log_stds  = (const float*)d_in[9];
    const float* W_mix       = (const float*)d_in[10];
    const float* W1f = (const float*)d_in[11];
    const float* b1f = (const float*)d_in[12];
    const float* W2f = (const float*)d_in[13];
    const float* b2f = (const float*)d_in[14];
    const float* W1e = (const float*)d_in[15];
    const float* b1e = (const float*)d_in[16];
    const float* W2e = (const float*)d_in[17];
    const float* b2e = (const float*)d_in[18];
    const float* W1d = (const float*)d_in[19];
    const float* b1d = (const float*)d_in[20];
    const float* W2d = (const float*)d_in[21];
    const float* b2d = (const float*)d_in[22];
    float* out = (float*)d_out;

    k0_ygrid<<<32, 128>>>();
    k1_cov<2><<<GG_, 320>>>(s_inter, bag, ptr, focus, W_bag);
    k1_cov<1><<<GG_, 320>>>(s_inter, bag, ptr, focus, W_bag);
    k1_cov0<<<GG_, 160>>>(s_inter, bag, ptr, focus, W_bag);
    k2_mlp<<<(NN_ + 31) / 32, 128>>>(W1f, b1f, W2f, b2f, W1e, b1e, W2e, b2e);
    k3_group<<<(GG_ + 3) / 4, 128>>>(bag, ptr, focus, element, out);
    k5_final<<<(GG_ + 3) / 4, 128>>>(ptr, focus, element, distance, orientation,
                                     W_mix, W1d, b1d, W2d, b2d, d_log_stds, out);
}

// round 7
// speedup vs baseline: 1.0020x; 1.0020x over previous
#include <cuda_runtime.h>
#include <cuda_bf16.h>
#include <math.h>

#define NN_ 50000
#define GG_ 2500
#define PGRID 4096
#define INV_SQMZ 0.04419417382415922f

typedef unsigned long long ull;

// ---------------- device scratch ----------------
__device__ float g_sinv[(size_t)NN_ * 384];   // per-node invariant norms
__device__ float g_scov[(size_t)GG_ * 1152];  // focused-node cov vectors (with /SQ_MZ)
__device__ float g_fl[NN_];                   // focus logits
__device__ float g_el[(size_t)NN_ * 4];       // element logits
__device__ float g_Y[9 * PGRID];              // SH basis on Fibonacci grid, [j][p]
__device__ float g_lp12[GG_];                 // lp_focus + lp_element

__device__ __forceinline__ float wsum(float v) {
#pragma unroll
    for (int s = 16; s > 0; s >>= 1) v += __shfl_xor_sync(0xffffffffu, v, s);
    return v;
}

__device__ __forceinline__ ull pk2(float lo, float hi) {
    ull r;
    asm("mov.b64 %0, {%1, %2};" : "=l"(r) : "f"(lo), "f"(hi));
    return r;
}
__device__ __forceinline__ void upk2(ull v, float& lo, float& hi) {
    asm("mov.b64 {%0, %1}, %2;" : "=f"(lo), "=f"(hi) : "l"(v));
}
__device__ __forceinline__ void fma2_(ull& d, ull a, ull b) {
    asm("fma.rn.f32x2 %0, %1, %2, %0;" : "+l"(d) : "l"(a), "l"(b));
}

// ---------------- K0: build Y_GRID ----------------
__global__ void k0_ygrid() {
    int i = blockIdx.x * blockDim.x + threadIdx.x;
    if (i >= PGRID) return;
    double ph = 3.14159265358979323846 * (3.0 - sqrt(5.0)) * (double)i;
    double z  = 1.0 - 2.0 * ((double)i + 0.5) / (double)PGRID;
    double rr = 1.0 - z * z; if (rr < 0.0) rr = 0.0;
    double r  = sqrt(rr);
    float x  = (float)(r * cos(ph));
    float y  = (float)(r * sin(ph));
    float zf = (float)z;
    g_Y[0 * PGRID + i] = 0.28209479177387814f;
    g_Y[1 * PGRID + i] = 0.4886025119029199f * y;
    g_Y[2 * PGRID + i] = 0.4886025119029199f * zf;
    g_Y[3 * PGRID + i] = 0.4886025119029199f * x;
    g_Y[4 * PGRID + i] = 1.0925484305920792f * x * y;
    g_Y[5 * PGRID + i] = 1.0925484305920792f * y * zf;
    g_Y[6 * PGRID + i] = 0.31539156525252005f * (3.f * zf * zf - 1.f);
    g_Y[7 * PGRID + i] = 1.0925484305920792f * x * zf;
    g_Y[8 * PGRID + i] = 0.5462742152960396f * (x * x - y * y);
}

// ---------------- K1 (L=1,2): per-group cov GEMM + norms ----------------
// 320 threads: cq = tid&63 -> cols {2cq, 2cq+1}; nq = tid>>6 -> nodes 4nq..4nq+3.
// FFMA2 lanes pair nodes; W pre-duplicated in smem; small tile -> high occupancy.
template <int L>
__global__ void __launch_bounds__(320, 2) k1_cov(
    const float* __restrict__ s_inter, const float* __restrict__ bag,
    const int* __restrict__ ptr, const int* __restrict__ focus,
    const float* __restrict__ W_bag)
{
    constexpr int OL  = (L == 1) ? 3 : 5;
    constexpr int OFF = (L == 1) ? 128 : 512;

    __shared__ __align__(16) float sW2[32 * 256];       // dup pairs [kk][col dup]
    __shared__ __align__(16) float sX[32 * OL * 20];    // [kk*OL+m][n]

    const int g   = blockIdx.x;
    const int tid = threadIdx.x;
    const int cq  = tid & 63;
    const int nq  = tid >> 6;
    const int n0  = ptr[g];
    const float b0 = bag[g * 4 + 0], b1 = bag[g * 4 + 1];
    const float b2 = bag[g * 4 + 2], b3 = bag[g * 4 + 3];
    const float* Wl = W_bag + (size_t)L * 65536;

    ull acc[2][2][OL];
#pragma unroll
    for (int cc = 0; cc < 2; cc++)
#pragma unroll
        for (int np = 0; np < 2; np++)
#pragma unroll
            for (int m = 0; m < OL; m++) acc[cc][np][m] = 0ull;

    for (int ic = 0; ic < 128; ic += 32) {
        // build dup'd W_eff chunk
        for (int e = tid; e < 1024; e += 320) {
            const int kk = e >> 5, c4 = (e & 31) << 2;
            const float* wp = Wl + (size_t)(ic + kk) * 512 + c4;
            const float4 w0 = *reinterpret_cast<const float4*>(wp);
            const float4 w1 = *reinterpret_cast<const float4*>(wp + 128);
            const float4 w2 = *reinterpret_cast<const float4*>(wp + 256);
            const float4 w3 = *reinterpret_cast<const float4*>(wp + 384);
            float4 r;
            r.x = fmaf(b0, w0.x, fmaf(b1, w1.x, fmaf(b2, w2.x, b3 * w3.x)));
            r.y = fmaf(b0, w0.y, fmaf(b1, w1.y, fmaf(b2, w2.y, b3 * w3.y)));
            r.z = fmaf(b0, w0.z, fmaf(b1, w1.z, fmaf(b2, w2.z, b3 * w3.z)));
            r.w = fmaf(b0, w0.w, fmaf(b1, w1.w, fmaf(b2, w2.w, b3 * w3.w)));
            *reinterpret_cast<float4*>(sW2 + kk * 256 + c4 * 2)     =
                make_float4(r.x, r.x, r.y, r.y);
            *reinterpret_cast<float4*>(sW2 + kk * 256 + c4 * 2 + 4) =
                make_float4(r.z, r.z, r.w, r.w);
        }
        // stage X chunk: sX[j*20 + nl], j = kk*OL + m
        for (int e = tid; e < 20 * 32 * OL; e += 320) {
            const int nl = e / (32 * OL);
            const int j  = e - nl * (32 * OL);
            sX[j * 20 + nl] = s_inter[(size_t)(n0 + nl) * 1152 + OFF + ic * OL + j];
        }
        __syncthreads();

        for (int kk = 0; kk < 32; kk++) {
            const ulonglong2 wv = *reinterpret_cast<const ulonglong2*>(
                sW2 + kk * 256 + cq * 4);
#pragma unroll
            for (int m = 0; m < OL; m++) {
                const ulonglong2 xv = *reinterpret_cast<const ulonglong2*>(
                    sX + (kk * OL + m) * 20 + nq * 4);
                fma2_(acc[0][0][m], wv.x, xv.x);
                fma2_(acc[0][1][m], wv.x, xv.y);
                fma2_(acc[1][0][m], wv.y, xv.x);
                fma2_(acc[1][1][m], wv.y, xv.y);
            }
        }
        __syncthreads();
    }

    const int foc = focus[g];
#pragma unroll
    for (int cc = 0; cc < 2; cc++) {
        const int col = cq * 2 + cc;
#pragma unroll
        for (int np = 0; np < 2; np++) {
            const int nloc = nq * 4 + np * 2;
            float s0 = 1e-12f, s1 = 1e-12f;
            float lo[OL], hi[OL];
#pragma unroll
            for (int m = 0; m < OL; m++) {
                float l, h;
                upk2(acc[cc][np][m], l, h);
                l *= INV_SQMZ; h *= INV_SQMZ;
                s0 = fmaf(l, l, s0); s1 = fmaf(h, h, s1);
                lo[m] = l; hi[m] = h;
            }
            const int na = n0 + nloc;
            g_sinv[(size_t)na * 384 + L * 128 + col]       = sqrtf(s0);
            g_sinv[(size_t)(na + 1) * 384 + L * 128 + col] = sqrtf(s1);
            if (nloc == foc) {
#pragma unroll
                for (int m = 0; m < OL; m++)
                    g_scov[(size_t)g * 1152 + OFF + col * OL + m] = lo[m];
            }
            if (nloc + 1 == foc) {
#pragma unroll
                for (int m = 0; m < OL; m++)
                    g_scov[(size_t)g * 1152 + OFF + col * OL + m] = hi[m];
            }
        }
    }
}

// ---------------- K1 (L=0): cols paired, X pre-duplicated ----------------
__global__ void __launch_bounds__(160, 4) k1_cov0(
    const float* __restrict__ s_inter, const float* __restrict__ bag,
    const int* __restrict__ ptr, const int* __restrict__ focus,
    const float* __restrict__ W_bag)
{
    __shared__ __align__(16) float sW[32 * 128];   // normal W_eff
    __shared__ __align__(16) float sX2[32 * 40];   // dup'd x: [kk][n dup]

    const int g   = blockIdx.x;
    const int tid = threadIdx.x;
    const int cq  = tid & 31;
    const int nq  = tid >> 5;
    const int n0  = ptr[g];
    const float b0 = bag[g * 4 + 0], b1 = bag[g * 4 + 1];
    const float b2 = bag[g * 4 + 2], b3 = bag[g * 4 + 3];
    const float* Wl = W_bag;

    ull acc[2][4];
#pragma unroll
    for (int cp = 0; cp < 2; cp++)
#pragma unroll
        for (int nl = 0; nl < 4; nl++) acc[cp][nl] = 0ull;

    for (int ic = 0; ic < 128; ic += 32) {
        for (int e = tid; e < 1024; e += 160) {
            const int kk = e >> 5, c4 = (e & 31) << 2;
            const float* wp = Wl + (size_t)(ic + kk) * 512 + c4;
            const float4 w0 = *reinterpret_cast<const float4*>(wp);
            const float4 w1 = *reinterpret_cast<const float4*>(wp + 128);
            const float4 w2 = *reinterpret_cast<const float4*>(wp + 256);
            const float4 w3 = *reinterpret_cast<const float4*>(wp + 384);
            float4 r;
            r.x = fmaf(b0, w0.x, fmaf(b1, w1.x, fmaf(b2, w2.x, b3 * w3.x)));
            r.y = fmaf(b0, w0.y, fmaf(b1, w1.y, fmaf(b2, w2.y, b3 * w3.y)));
            r.z = fmaf(b0, w0.z, fmaf(b1, w1.z, fmaf(b2, w2.z, b3 * w3.z)));
            r.w = fmaf(b0, w0.w, fmaf(b1, w1.w, fmaf(b2, w2.w, b3 * w3.w)));
            *reinterpret_cast<float4*>(sW + kk * 128 + c4) = r;
        }
        for (int e = tid; e < 640; e += 160) {
            const int nl = e >> 5, kk = e & 31;
            const float v = s_inter[(size_t)(n0 + nl) * 1152 + ic + kk];
            *reinterpret_cast<float2*>(sX2 + kk * 40 + nl * 2) = make_float2(v, v);
        }
        __syncthreads();

        for (int kk = 0; kk < 32; kk++) {
            const ulonglong2 wv = *reinterpret_cast<const ulonglong2*>(sW + kk * 128 + cq * 4);
            const ulonglong2 xa = *reinterpret_cast<const ulonglong2*>(sX2 + kk * 40 + nq * 8);
            const ulonglong2 xb = *reinterpret_cast<const ulonglong2*>(sX2 + kk * 40 + nq * 8 + 4);
            fma2_(acc[0][0], wv.x, xa.x); fma2_(acc[1][0], wv.y, xa.x);
            fma2_(acc[0][1], wv.x, xa.y); fma2_(acc[1][1], wv.y, xa.y);
            fma2_(acc[0][2], wv.x, xb.x); fma2_(acc[1][2], wv.y, xb.x);
            fma2_(acc[0][3], wv.x, xb.y); fma2_(acc[1][3], wv.y, xb.y);
        }
        __syncthreads();
    }

    const int foc = focus[g];
#pragma unroll
    for (int cp = 0; cp < 2; cp++) {
        const int col0 = cq * 4 + cp * 2;
#pragma unroll
        for (int nl = 0; nl < 4; nl++) {
            float c0, c1;
            upk2(acc[cp][nl], c0, c1);
            c0 *= INV_SQMZ; c1 *= INV_SQMZ;
            const int n = n0 + nq * 4 + nl;
            g_sinv[(size_t)n * 384 + col0]     = sqrtf(fmaf(c0, c0, 1e-12f));
            g_sinv[(size_t)n * 384 + col0 + 1] = sqrtf(fmaf(c1, c1, 1e-12f));
            if (nq * 4 + nl == foc) {
                g_scov[(size_t)g * 1152 + col0]     = c0;
                g_scov[(size_t)g * 1152 + col0 + 1] = c1;
            }
        }
    }
}

// ---------------- K2: fused focus + element MLPs ----------------
__global__ void __launch_bounds__(128, 4) k2_mlp(
    const float* __restrict__ gW1f, const float* __restrict__ gb1f,
    const float* __restrict__ gW2f, const float* __restrict__ gb2f,
    const float* __restrict__ gW1e, const float* __restrict__ gb1e,
    const float* __restrict__ gW2e, const float* __restrict__ gb2e)
{
    __shared__ __align__(16) float sS[384 * 32];     // [k][nn]
    const int tid = threadIdx.x;
    const int nb  = blockIdx.x * 32;
    for (int e = tid; e < 96 * 32; e += 128) {
        const int kq = e >> 5, nn = e & 31;
        const int nglob = nb + nn;
        float4 v = make_float4(0.f, 0.f, 0.f, 0.f);
        if (nglob < NN_)
            v = *reinterpret_cast<const float4*>(g_sinv + (size_t)nglob * 384 + kq * 4);
        sS[(kq * 4 + 0) * 32 + nn] = v.x;
        sS[(kq * 4 + 1) * 32 + nn] = v.y;
        sS[(kq * 4 + 2) * 32 + nn] = v.z;
        sS[(kq * 4 + 3) * 32 + nn] = v.w;
    }
    __syncthreads();

    const float bf = gb1f[tid], be = gb1e[tid];
    ull acc2f[16], acc2e[16];
#pragma unroll
    for (int p = 0; p < 16; p++) { acc2f[p] = pk2(bf, bf); acc2e[p] = pk2(be, be); }

    for (int k0 = 0; k0 < 384; k0 += 4) {
        float wf[4], we[4];
#pragma unroll
        for (int q = 0; q < 4; q++) {
            wf[q] = gW1f[(k0 + q) * 128 + tid];
            we[q] = gW1e[(k0 + q) * 128 + tid];
        }
#pragma unroll
        for (int q = 0; q < 4; q++) {
            const ull wf2 = pk2(wf[q], wf[q]);
            const ull we2 = pk2(we[q], we[q]);
            const ulonglong2* x2 = reinterpret_cast<const ulonglong2*>(sS + (k0 + q) * 32);
#pragma unroll
            for (int p8 = 0; p8 < 8; p8++) {
                const ulonglong2 xx = x2[p8];
                fma2_(acc2f[p8 * 2 + 0], wf2, xx.x);
                fma2_(acc2f[p8 * 2 + 1], wf2, xx.y);
                fma2_(acc2e[p8 * 2 + 0], we2, xx.x);
                fma2_(acc2e[p8 * 2 + 1], we2, xx.y);
            }
        }
    }

    float accf[32], acce[32];
#pragma unroll
    for (int p = 0; p < 16; p++) {
        upk2(acc2f[p], accf[2 * p], accf[2 * p + 1]);
        upk2(acc2e[p], acce[2 * p], acce[2 * p + 1]);
    }

    const float w2f = gW2f[tid];
    float w2e[4];
#pragma unroll
    for (int z = 0; z < 4; z++) w2e[z] = gW2e[tid * 4 + z];
    const int lane = tid & 31, wid = tid >> 5;
    __syncthreads();
    float* sR = sS;
    for (int nn = 0; nn < 32; nn++) {
        const float hf = fmaxf(accf[nn], 0.f);
        const float he = fmaxf(acce[nn], 0.f);
        float v0 = hf * w2f, v1 = he * w2e[0], v2 = he * w2e[1],
              v3 = he * w2e[2], v4 = he * w2e[3];
#pragma unroll
        for (int s = 16; s > 0; s >>= 1) {
            v0 += __shfl_down_sync(0xffffffffu, v0, s);
            v1 += __shfl_down_sync(0xffffffffu, v1, s);
            v2 += __shfl_down_sync(0xffffffffu, v2, s);
            v3 += __shfl_down_sync(0xffffffffu, v3, s);
            v4 += __shfl_down_sync(0xffffffffu, v4, s);
        }
        if (lane == 0) {
            const int base = (wid * 32 + nn) * 5;
            sR[base + 0] = v0; sR[base + 1] = v1; sR[base + 2] = v2;
            sR[base + 3] = v3; sR[base + 4] = v4;
        }
    }
    __syncthreads();
    if (tid < 32) {
        const int nglob = nb + tid;
        if (nglob < NN_) {
            float f = gb2f[0];
#pragma unroll
            for (int w = 0; w < 4; w++) f += sR[(w * 32 + tid) * 5 + 0];
            g_fl[nglob] = f;
#pragma unroll
            for (int z = 0; z < 4; z++) {
                float e = gb2e[z];
#pragma unroll
                for (int w = 0; w < 4; w++) e += sR[(w * 32 + tid) * 5 + 1 + z];
                g_el[(size_t)nglob * 4 + z] = e;
            }
        }
    }
}

// ---------------- K3: group softmaxes / entropies ----------------
__global__ void __launch_bounds__(128) k3_group(
    const float* __restrict__ bag, const int* __restrict__ ptr,
    const int* __restrict__ focus, const int* __restrict__ element,
    float* __restrict__ out)
{
    const int g = blockIdx.x * 4 + (threadIdx.x >> 5);
    const int lane = threadIdx.x & 31;
    if (g >= GG_) return;
    const int n0 = ptr[g];
    const int cnt = ptr[g + 1] - n0;
    const int foc = focus[g];
    const int zel = element[g];
    const bool valid = lane < cnt;
    const int n = n0 + lane;
    float f = valid ? g_fl[n] : -3.0e38f;
    float mx = f;
#pragma unroll
    for (int s = 16; s > 0; s >>= 1) mx = fmaxf(mx, __shfl_xor_sync(0xffffffffu, mx, s));
    const float ex = valid ? expf(f - mx) : 0.f;
    const float S  = wsum(ex);
    const float fp = ex / S;
    const float hfocus = wsum(valid ? -fp * logf(fp + 1e-20f) : 0.f);
    float hel = 0.f, pzel = 0.f;
    if (valid) {
        float lz[4];
        float m4 = -3.0e38f;
#pragma unroll
        for (int z = 0; z < 4; z++) {
            float v = g_el[(size_t)n * 4 + z];
            v = (bag[g * 4 + z] > 0.f) ? v : -1e9f;
            lz[z] = v; m4 = fmaxf(m4, v);
        }
        float s4 = 0.f;
#pragma unroll
        for (int z = 0; z < 4; z++) { lz[z] = expf(lz[z] - m4); s4 += lz[z]; }
#pragma unroll
        for (int z = 0; z < 4; z++) {
            lz[z] /= s4;
            hel -= lz[z] * logf(fmaxf(lz[z], 1e-20f));
        }
        pzel = lz[zel];
    }
    const float hef = wsum(fp * hel);
    const float lp = wsum((valid && lane == foc)
                          ? (logf(fp + 1e-20f) + logf(pzel + 1e-20f)) : 0.f);
    if (lane == 0) { g_lp12[g] = lp; out[2 * g + 1] = hfocus + hef; }
}

// ---------------- K5: distance MLP/GMM + cond + orientation logZ ----------------
__global__ void __launch_bounds__(128) k5_final(
    const int* __restrict__ ptr, const int* __restrict__ focus,
    const int* __restrict__ element, const float* __restrict__ distance,
    const float* __restrict__ orientation, const float* __restrict__ W_mix,
    const float* __restrict__ W1d, const float* __restrict__ b1d,
    const float* __restrict__ W2d, const float* __restrict__ b2d,
    const float* __restrict__ d_log_stds, float* __restrict__ out)
{
    const int tid = threadIdx.x, lane = tid & 31, wq = tid >> 5;
    const int gbase = blockIdx.x * 4;
    __shared__ float sSI[4][384];
    __shared__ int   sGI[4], sEl[4];
    __shared__ float sRed[4][4][6];
    if (tid < 4) {
        const int g = gbase + tid;
        sGI[tid] = (g < GG_) ? (ptr[g] + focus[g]) : 0;
        sEl[tid] = (g < GG_) ? element[g] : 0;
    }
    __syncthreads();
#pragma unroll
    for (int q = 0; q < 4; q++)
        for (int k = tid; k < 384; k += 128)
            sSI[q][k] = g_sinv[(size_t)sGI[q] * 384 + k];
    __syncthreads();

    float acc[4];
    const float b1 = b1d[tid];
#pragma unroll
    for (int q = 0; q < 4; q++) acc[q] = b1;
    for (int k = 0; k < 384; k++) {
        const float w = W1d[k * 128 + tid];
#pragma unroll
        for (int q = 0; q < 4; q++) acc[q] = fmaf(w, sSI[q][k], acc[q]);
    }
#pragma unroll
    for (int q = 0; q < 4; q++) acc[q] += W1d[(384 + sEl[q]) * 128 + tid];

    float w2[6];
#pragma unroll
    for (int j = 0; j < 6; j++) w2[j] = W2d[tid * 6 + j];
#pragma unroll
    for (int q = 0; q < 4; q++) {
        const float h = fmaxf(acc[q], 0.f);
        float v[6];
#pragma unroll
        for (int j = 0; j < 6; j++) v[j] = h * w2[j];
#pragma unroll
        for (int s = 16; s > 0; s >>= 1)
#pragma unroll
            for (int j = 0; j < 6; j++) v[j] += __shfl_down_sync(0xffffffffu, v[j], s);
        if (lane == 0)
#pragma unroll
            for (int j = 0; j < 6; j++) sRed[wq][q][j] = v[j];
    }
    __syncthreads();

    const int g = gbase + wq;
    if (g >= GG_) return;
    float hj[6];
#pragma unroll
    for (int j = 0; j < 6; j++)
        hj[j] = sRed[0][wq][j] + sRed[1][wq][j] + sRed[2][wq][j] + sRed[3][wq][j] + b2d[j];

    const float d = distance[g];
    float lm = fmaxf(hj[0], fmaxf(hj[1], hj[2]));
    float se = expf(hj[0] - lm) + expf(hj[1] - lm) + expf(hj[2] - lm);
    const float lse = lm + logf(se);
    float aj[3];
#pragma unroll
    for (int j = 0; j < 3; j++) {
        const float mean = tanhf(hj[3 + j]) * 0.45f + 1.35f;
        const float std  = fmaxf(expf(d_log_stds[j]), 1e-6f);
        const float t = (d - mean) / std;
        aj[j] = (hj[j] - lse) - 0.5f * t * t - logf(std) - 0.91893853320467274f;
    }
    float am = fmaxf(aj[0], fmaxf(aj[1], aj[2]));
    const float lp_dist = am + logf(expf(aj[0] - am) + expf(aj[1] - am) + expf(aj[2] - am));

    float bess[8];
#pragma unroll
    for (int k = 0; k < 8; k++)
        bess[k] = 1.0540925533894598f * sinf((float)(k + 1) * 3.14159265358979f * d / 1.8f) / d;

    const int zel = sEl[wq];
    float cond[9];
#pragma unroll
    for (int j = 0; j < 9; j++) cond[j] = 0.f;
    const float* scov = g_scov + (size_t)g * 1152;
#pragma unroll
    for (int ib = 0; ib < 4; ib++) {
        const int i = lane + ib * 32;
        {
            float tw = 0.f;
#pragma unroll
            for (int k = 0; k < 8; k++)
                tw = fmaf(bess[k], W_mix[k * 1536 + 0 * 512 + i * 4 + zel], tw);
            tw *= 0.3535533905932738f;
            cond[0] = fmaf(scov[i], tw, cond[0]);
        }
        {
            float tw = 0.f;
#pragma unroll
            for (int k = 0; k < 8; k++)
                tw = fmaf(bess[k], W_mix[k * 1536 + 1 * 512 + i * 4 + zel], tw);
            tw *= 0.3535533905932738f;
#pragma unroll
            for (int m = 0; m < 3; m++)
                cond[1 + m] = fmaf(scov[128 + i * 3 + m], tw, cond[1 + m]);
        }
        {
            float tw = 0.f;
#pragma unroll
            for (int k = 0; k < 8; k++)
                tw = fmaf(bess[k], W_mix[k * 1536 + 2 * 512 + i * 4 + zel], tw);
            tw *= 0.3535533905932738f;
#pragma unroll
            for (int m = 0; m < 5; m++)
                cond[4 + m] = fmaf(scov[512 + i * 5 + m], tw, cond[4 + m]);
        }
    }
#pragma unroll
    for (int j = 0; j < 9; j++) cond[j] = wsum(cond[j]) * INV_SQMZ;

    float m_run = -3.0e38f, s_run = 0.f;
    for (int t = 0; t < 128; t++) {
        const int p = lane + 32 * t;
        float f = 0.f;
#pragma unroll
        for (int j = 0; j < 9; j++) f = fmaf(cond[j], g_Y[j * PGRID + p], f);
        f *= 10.0f;
        const float nm = fmaxf(m_run, f);
        s_run = s_run * __expf(m_run - nm) + __expf(f - nm);
        m_run = nm;
    }
#pragma unroll
    for (int s = 16; s > 0; s >>= 1) {
        const float om = __shfl_xor_sync(0xffffffffu, m_run, s);
        const float os = __shfl_xor_sync(0xffffffffu, s_run, s);
        const float nm = fmaxf(m_run, om);
        s_run = s_run * __expf(m_run - nm) + os * __expf(om - nm);
        m_run = nm;
    }
    const float logZ = m_run + logf(s_run) - 8.317766166719343f + 2.5310242469692907f;

    if (lane == 0) {
        float ox = orientation[g * 3 + 0], oy = orientation[g * 3 + 1],
              oz = orientation[g * 3 + 2];
        const float inv = rsqrtf(ox * ox + oy * oy + oz * oz);
        ox *= inv; oy *= inv; oz *= inv;
        float sh[9];
        sh[0] = 0.28209479177387814f;
        sh[1] = 0.4886025119029199f * oy;
        sh[2] = 0.4886025119029199f * oz;
        sh[3] = 0.4886025119029199f * ox;
        sh[4] = 1.0925484305920792f * ox * oy;
        sh[5] = 1.0925484305920792f * oy * oz;
        sh[6] = 0.31539156525252005f * (3.f * oz * oz - 1.f);
        sh[7] = 1.0925484305920792f * ox * oz;
        sh[8] = 0.5462742152960396f * (ox * ox - oy * oy);
        float f_x = 0.f;
#pragma unroll
        for (int j = 0; j < 9; j++) f_x = fmaf(cond[j], sh[j], f_x);
        const float lp_ori = 10.0f * f_x - logZ;
        out[2 * g] = g_lp12[g] + lp_dist + lp_ori;
    }
}

// ---------------- launch ----------------
extern "C" void kernel_launch(void* const* d_in, const int* in_sizes, int n_in,
                              void* d_out, int out_size) {
    const float* s_inter     = (const float*)d_in[0];
    const float* bag         = (const float*)d_in[1];
    const int*   ptr         = (const int*)  d_in[3];
    const int*   focus       = (const int*)  d_in[4];
    const int*   element     = (const int*)  d_in[5];
    const float* distance    = (const float*)d_in[6];
    const float* orientation = (const float*)d_in[7];
    const float* W_bag       = (const float*)d_in[8];
    const float* d_log_stds  = (const float*)d_in[9];
    const float* W_mix       = (const float*)d_in[10];
    const float* W1f = (const float*)d_in[11];
    const float* b1f = (const float*)d_in[12];
    const float* W2f = (const float*)d_in[13];
    const float* b2f = (const float*)d_in[14];
    const float* W1e = (const float*)d_in[15];
    const float* b1e = (const float*)d_in[16];
    const float* W2e = (const float*)d_in[17];
    const float* b2e = (const float*)d_in[18];
    const float* W1d = (const float*)d_in[19];
    const float* b1d = (const float*)d_in[20];
    const float* W2d = (const float*)d_in[21];
    const float* b2d = (const float*)d_in[22];
    float* out = (float*)d_out;

    k0_ygrid<<<32, 128>>>();
    k1_cov<2><<<GG_, 320>>>(s_inter, bag, ptr, focus, W_bag);
    k1_cov<1><<<GG_, 320>>>(s_inter, bag, ptr, focus, W_bag);
    k1_cov0<<<GG_, 160>>>(s_inter, bag, ptr, focus, W_bag);
    k2_mlp<<<(NN_ + 31) / 32, 128>>>(W1f, b1f, W2f, b2f, W1e, b1e, W2e, b2e);
    k3_group<<<(GG_ + 3) / 4, 128>>>(bag, ptr, focus, element, out);
    k5_final<<<(GG_ + 3) / 4, 128>>>(ptr, focus, element, distance, orientation,
                                     W_mix, W1d, b1d, W2d, b2d, d_log_stds, out);
}

// round 12
// speedup vs baseline: 1.1527x; 1.1504x over previous
#include <cuda_runtime.h>
#include <cuda_bf16.h>
#include <math.h>
#include <stdint.h>

#define NN_ 50000
#define GG_ 2500
#define PGRID 4096
#define INV_SQMZ 0.04419417382415922f

typedef unsigned long long ull;

// ---------------- device scratch ----------------
__device__ float g_sinv[(size_t)NN_ * 384];   // per-node invariant norms
__device__ float g_scov[(size_t)GG_ * 1152];  // focused-node cov vectors (with /SQ_MZ)
__device__ float g_fl[NN_];                   // focus logits
__device__ float g_el[(size_t)NN_ * 4];       // element logits
__device__ float g_Y[9 * PGRID];              // SH basis on Fibonacci grid, [j][p]
__device__ float g_lp12[GG_];                 // lp_focus + lp_element
__device__ float g_weff[(size_t)GG_ * 3 * 16384];  // folded per-group weights [g*3+l][i*128+o]

__device__ __forceinline__ float wsum(float v) {
#pragma unroll
    for (int s = 16; s > 0; s >>= 1) v += __shfl_xor_sync(0xffffffffu, v, s);
    return v;
}

__device__ __forceinline__ ull pk2(float lo, float hi) {
    ull r;
    asm("mov.b64 %0, {%1, %2};" : "=l"(r) : "f"(lo), "f"(hi));
    return r;
}
__device__ __forceinline__ void upk2(ull v, float& lo, float& hi) {
    asm("mov.b64 {%0, %1}, %2;" : "=f"(lo), "=f"(hi) : "l"(v));
}
__device__ __forceinline__ void fma2_(ull& d, ull a, ull b) {
    asm("fma.rn.f32x2 %0, %1, %2, %0;" : "+l"(d) : "l"(a), "l"(b));
}
__device__ __forceinline__ unsigned int smem_u32(const void* p) {
    return (unsigned int)__cvta_generic_to_shared(p);
}
__device__ __forceinline__ void cpa16(unsigned int dst, const float* src) {
    asm volatile("cp.async.ca.shared.global [%0], [%1], 16;" :: "r"(dst), "l"(src));
}
#define CP_COMMIT() asm volatile("cp.async.commit_group;")
#define CP_WAIT(N)  asm volatile("cp.async.wait_group %0;" :: "n"(N))

// ---------------- K0: build Y_GRID ----------------
__global__ void k0_ygrid() {
    int i = blockIdx.x * blockDim.x + threadIdx.x;
    if (i >= PGRID) return;
    double ph = 3.14159265358979323846 * (3.0 - sqrt(5.0)) * (double)i;
    double z  = 1.0 - 2.0 * ((double)i + 0.5) / (double)PGRID;
    double rr = 1.0 - z * z; if (rr < 0.0) rr = 0.0;
    double r  = sqrt(rr);
    float x  = (float)(r * cos(ph));
    float y  = (float)(r * sin(ph));
    float zf = (float)z;
    g_Y[0 * PGRID + i] = 0.28209479177387814f;
    g_Y[1 * PGRID + i] = 0.4886025119029199f * y;
    g_Y[2 * PGRID + i] = 0.4886025119029199f * zf;
    g_Y[3 * PGRID + i] = 0.4886025119029199f * x;
    g_Y[4 * PGRID + i] = 1.0925484305920792f * x * y;
    g_Y[5 * PGRID + i] = 1.0925484305920792f * y * zf;
    g_Y[6 * PGRID + i] = 0.31539156525252005f * (3.f * zf * zf - 1.f);
    g_Y[7 * PGRID + i] = 1.0925484305920792f * x * zf;
    g_Y[8 * PGRID + i] = 0.5462742152960396f * (x * x - y * y);
}

// ---------------- kW: fold bag into W_bag for all (g, l) ----------------
__global__ void __launch_bounds__(256) kW(
    const float* __restrict__ W_bag, const float* __restrict__ bag)
{
    const int gl = blockIdx.x;           // 0..7499
    const int g  = gl / 3;
    const int l  = gl - g * 3;
    const float b0 = bag[g * 4 + 0], b1 = bag[g * 4 + 1];
    const float b2 = bag[g * 4 + 2], b3 = bag[g * 4 + 3];
    const float* Wl = W_bag + (size_t)l * 65536;
    float* dst = g_weff + (size_t)gl * 16384;
    for (int e = threadIdx.x; e < 4096; e += 256) {
        const int i  = e >> 5;
        const int o4 = (e & 31) << 2;
        const float* wp = Wl + (size_t)i * 512 + o4;
        const float4 w0 = *reinterpret_cast<const float4*>(wp);
        const float4 w1 = *reinterpret_cast<const float4*>(wp + 128);
        const float4 w2 = *reinterpret_cast<const float4*>(wp + 256);
        const float4 w3 = *reinterpret_cast<const float4*>(wp + 384);
        float4 r;
        r.x = fmaf(b0, w0.x, fmaf(b1, w1.x, fmaf(b2, w2.x, b3 * w3.x)));
        r.y = fmaf(b0, w0.y, fmaf(b1, w1.y, fmaf(b2, w2.y, b3 * w3.y)));
        r.z = fmaf(b0, w0.z, fmaf(b1, w1.z, fmaf(b2, w2.z, b3 * w3.z)));
        r.w = fmaf(b0, w0.w, fmaf(b1, w1.w, fmaf(b2, w2.w, b3 * w3.w)));
        *reinterpret_cast<float4*>(dst + i * 128 + o4) = r;
    }
}

// ---------------- K1: pipelined per-group cov GEMM + norms ----------------
// 320 threads: cq = tid&63 -> cols {2cq, 2cq+1}; nq = tid>>6 -> nodes 4nq..4nq+3.
// Double-buffered SMEM; W via cp.async from g_weff; X via register prefetch.
template <int OL>
__device__ __forceinline__ void k1_compute(
    const float* __restrict__ sWb, const float* __restrict__ sXb,
    int cq, int nq, ull (&acc)[2][2][OL])
{
    const float* wp = sWb + cq * 2;
    const float* xp = sXb + nq * 4;
#pragma unroll 8
    for (int kk = 0; kk < 32; kk++) {
        const float2 w = *reinterpret_cast<const float2*>(wp + kk * 128);
        const ull wd0 = pk2(w.x, w.x);
        const ull wd1 = pk2(w.y, w.y);
#pragma unroll
        for (int m = 0; m < OL; m++) {
            const ulonglong2 xv = *reinterpret_cast<const ulonglong2*>(
                xp + (kk * OL + m) * 20);
            fma2_(acc[0][0][m], wd0, xv.x);
            fma2_(acc[0][1][m], wd0, xv.y);
            fma2_(acc[1][0][m], wd1, xv.x);
            fma2_(acc[1][1][m], wd1, xv.y);
        }
    }
}

template <int L>
__global__ void __launch_bounds__(320, 2) k1_cov(
    const float* __restrict__ s_inter,
    const int* __restrict__ ptr, const int* __restrict__ focus)
{
    constexpr int OL  = (L == 0) ? 1 : (L == 1 ? 3 : 5);
    constexpr int OFF = (L == 0) ? 0 : (L == 1 ? 128 : 512);
    constexpr int XCH = 32 * OL;            // floats per node per chunk
    constexpr int NPT = (20 * XCH) / 320;   // exact: 2 / 6 / 10

    __shared__ __align__(16) float sW[2][32 * 128];
    __shared__ __align__(16) float sX[2][OL * 32 * 20];

    const int g   = blockIdx.x;
    const int tid = threadIdx.x;
    const int cq  = tid & 63;
    const int nq  = tid >> 6;
    const int n0  = ptr[g];
    const float* Wg = g_weff + ((size_t)g * 3 + L) * 16384;
    const float* Xg = s_inter + (size_t)n0 * 1152 + OFF;

    ull acc[2][2][OL];
#pragma unroll
    for (int cc = 0; cc < 2; cc++)
#pragma unroll
        for (int np = 0; np < 2; np++)
#pragma unroll
            for (int m = 0; m < OL; m++) acc[cc][np][m] = 0ull;

    float xr[NPT];

    // ---- X chunk -> regs ----
#define LDX(C)                                                            \
    {                                                                     \
        const float* src = Xg + (C) * XCH;                                \
        _Pragma("unroll")                                                 \
        for (int t = 0; t < NPT; t++) {                                   \
            const int idx = tid + t * 320;                                \
            const int nl = idx / XCH;                                     \
            const int j  = idx - nl * XCH;                                \
            xr[t] = src[(size_t)nl * 1152 + j];                           \
        }                                                                 \
    }
    // ---- X regs -> smem (transposed) ----
#define STX(B)                                                            \
    {                                                                     \
        _Pragma("unroll")                                                 \
        for (int t = 0; t < NPT; t++) {                                   \
            const int idx = tid + t * 320;                                \
            const int nl = idx / XCH;                                     \
            const int j  = idx - nl * XCH;                                \
            sX[B][j * 20 + nl] = xr[t];                                   \
        }                                                                 \
    }
    // ---- W chunk -> smem via cp.async ----
#define CPW(C, B)                                                         \
    {                                                                     \
        const unsigned int d = smem_u32(&sW[B][0]);                       \
        const float* s = Wg + (C) * 4096;                                 \
        for (int t = tid; t < 1024; t += 320) cpa16(d + t * 16, s + t * 4); \
        CP_COMMIT();                                                      \
    }

    // ---- preamble ----
    LDX(0);
    CPW(0, 0);
    STX(0);
    LDX(1);
    CPW(1, 1);
    CP_WAIT(1);            // W0 ready
    __syncthreads();       // X0 + W0 visible

    // ---- c = 0 ----
    STX(1);                // X1 -> buf1 (untouched)
    LDX(2);
    k1_compute<OL>(sW[0], sX[0], cq, nq, acc);
    CP_WAIT(0);            // W1 ready
    __syncthreads();

    // ---- c = 1 ----
    CPW(2, 0);
    STX(0);                // X2 -> buf0
    LDX(3);
    k1_compute<OL>(sW[1], sX[1], cq, nq, acc);
    CP_WAIT(0);            // W2 ready
    __syncthreads();

    // ---- c = 2 ----
    CPW(3, 1);
    STX(1);                // X3 -> buf1
    k1_compute<OL>(sW[0], sX[0], cq, nq, acc);
    CP_WAIT(0);            // W3 ready
    __syncthreads();

    // ---- c = 3 ----
    k1_compute<OL>(sW[1], sX[1], cq, nq, acc);

#undef LDX
#undef STX
#undef CPW

    // ---- epilogue: norms for all (n,o); cov for focused node ----
    const int foc = focus[g];
#pragma unroll
    for (int cc = 0; cc < 2; cc++) {
        const int col = cq * 2 + cc;
#pragma unroll
        for (int np = 0; np < 2; np++) {
            const int nloc = nq * 4 + np * 2;
            float s0 = 1e-12f, s1 = 1e-12f;
            float lo[OL], hi[OL];
#pragma unroll
            for (int m = 0; m < OL; m++) {
                float l, h;
                upk2(acc[cc][np][m], l, h);
                l *= INV_SQMZ; h *= INV_SQMZ;
                s0 = fmaf(l, l, s0); s1 = fmaf(h, h, s1);
                lo[m] = l; hi[m] = h;
            }
            const int na = n0 + nloc;
            g_sinv[(size_t)na * 384 + L * 128 + col]       = sqrtf(s0);
            g_sinv[(size_t)(na + 1) * 384 + L * 128 + col] = sqrtf(s1);
            if (nloc == foc) {
#pragma unroll
                for (int m = 0; m < OL; m++)
                    g_scov[(size_t)g * 1152 + OFF + col * OL + m] = lo[m];
            }
            if (nloc + 1 == foc) {
#pragma unroll
                for (int m = 0; m < OL; m++)
                    g_scov[(size_t)g * 1152 + OFF + col * OL + m] = hi[m];
            }
        }
    }
}

// ---------------- K2: fused focus + element MLPs ----------------
__global__ void __launch_bounds__(128, 4) k2_mlp(
    const float* __restrict__ gW1f, const float* __restrict__ gb1f,
    const float* __restrict__ gW2f, const float* __restrict__ gb2f,
    const float* __restrict__ gW1e, const float* __restrict__ gb1e,
    const float* __restrict__ gW2e, const float* __restrict__ gb2e)
{
    __shared__ __align__(16) float sS[384 * 32];     // [k][nn]
    const int tid = threadIdx.x;
    const int nb  = blockIdx.x * 32;
    for (int e = tid; e < 96 * 32; e += 128) {
        const int kq = e >> 5, nn = e & 31;
        const int nglob = nb + nn;
        float4 v = make_float4(0.f, 0.f, 0.f, 0.f);
        if (nglob < NN_)
            v = *reinterpret_cast<const float4*>(g_sinv + (size_t)nglob * 384 + kq * 4);
        sS[(kq * 4 + 0) * 32 + nn] = v.x;
        sS[(kq * 4 + 1) * 32 + nn] = v.y;
        sS[(kq * 4 + 2) * 32 + nn] = v.z;
        sS[(kq * 4 + 3) * 32 + nn] = v.w;
    }
    __syncthreads();

    const float bf = gb1f[tid], be = gb1e[tid];
    ull acc2f[16], acc2e[16];
#pragma unroll
    for (int p = 0; p < 16; p++) { acc2f[p] = pk2(bf, bf); acc2e[p] = pk2(be, be); }

    for (int k0 = 0; k0 < 384; k0 += 4) {
        float wf[4], we[4];
#pragma unroll
        for (int q = 0; q < 4; q++) {
            wf[q] = gW1f[(k0 + q) * 128 + tid];
            we[q] = gW1e[(k0 + q) * 128 + tid];
        }
#pragma unroll
        for (int q = 0; q < 4; q++) {
            const ull wf2 = pk2(wf[q], wf[q]);
            const ull we2 = pk2(we[q], we[q]);
            const ulonglong2* x2 = reinterpret_cast<const ulonglong2*>(sS + (k0 + q) * 32);
#pragma unroll
            for (int p8 = 0; p8 < 8; p8++) {
                const ulonglong2 xx = x2[p8];
                fma2_(acc2f[p8 * 2 + 0], wf2, xx.x);
                fma2_(acc2f[p8 * 2 + 1], wf2, xx.y);
                fma2_(acc2e[p8 * 2 + 0], we2, xx.x);
                fma2_(acc2e[p8 * 2 + 1], we2, xx.y);
            }
        }
    }

    float accf[32], acce[32];
#pragma unroll
    for (int p = 0; p < 16; p++) {
        upk2(acc2f[p], accf[2 * p], accf[2 * p + 1]);
        upk2(acc2e[p], acce[2 * p], acce[2 * p + 1]);
    }

    const float w2f = gW2f[tid];
    float w2e[4];
#pragma unroll
    for (int z = 0; z < 4; z++) w2e[z] = gW2e[tid * 4 + z];
    const int lane = tid & 31, wid = tid >> 5;
    __syncthreads();
    float* sR = sS;
    for (int nn = 0; nn < 32; nn++) {
        const float hf = fmaxf(accf[nn], 0.f);
        const float he = fmaxf(acce[nn], 0.f);
        float v0 = hf * w2f, v1 = he * w2e[0], v2 = he * w2e[1],
              v3 = he * w2e[2], v4 = he * w2e[3];
#pragma unroll
        for (int s = 16; s > 0; s >>= 1) {
            v0 += __shfl_down_sync(0xffffffffu, v0, s);
            v1 += __shfl_down_sync(0xffffffffu, v1, s);
            v2 += __shfl_down_sync(0xffffffffu, v2, s);
            v3 += __shfl_down_sync(0xffffffffu, v3, s);
            v4 += __shfl_down_sync(0xffffffffu, v4, s);
        }
        if (lane == 0) {
            const int base = (wid * 32 + nn) * 5;
            sR[base + 0] = v0; sR[base + 1] = v1; sR[base + 2] = v2;
            sR[base + 3] = v3; sR[base + 4] = v4;
        }
    }
    __syncthreads();
    if (tid < 32) {
        const int nglob = nb + tid;
        if (nglob < NN_) {
            float f = gb2f[0];
#pragma unroll
            for (int w = 0; w < 4; w++) f += sR[(w * 32 + tid) * 5 + 0];
            g_fl[nglob] = f;
#pragma unroll
            for (int z = 0; z < 4; z++) {
                float e = gb2e[z];
#pragma unroll
                for (int w = 0; w < 4; w++) e += sR[(w * 32 + tid) * 5 + 1 + z];
                g_el[(size_t)nglob * 4 + z] = e;
            }
        }
    }
}

// ---------------- K3: group softmaxes / entropies ----------------
__global__ void __launch_bounds__(128) k3_group(
    const float* __restrict__ bag, const int* __restrict__ ptr,
    const int* __restrict__ focus, const int* __restrict__ element,
    float* __restrict__ out)
{
    const int g = blockIdx.x * 4 + (threadIdx.x >> 5);
    const int lane = threadIdx.x & 31;
    if (g >= GG_) return;
    const int n0 = ptr[g];
    const int cnt = ptr[g + 1] - n0;
    const int foc = focus[g];
    const int zel = element[g];
    const bool valid = lane < cnt;
    const int n = n0 + lane;
    float f = valid ? g_fl[n] : -3.0e38f;
    float mx = f;
#pragma unroll
    for (int s = 16; s > 0; s >>= 1) mx = fmaxf(mx, __shfl_xor_sync(0xffffffffu, mx, s));
    const float ex = valid ? expf(f - mx) : 0.f;
    const float S  = wsum(ex);
    const float fp = ex / S;
    const float hfocus = wsum(valid ? -fp * logf(fp + 1e-20f) : 0.f);
    float hel = 0.f, pzel = 0.f;
    if (valid) {
        float lz[4];
        float m4 = -3.0e38f;
#pragma unroll
        for (int z = 0; z < 4; z++) {
            float v = g_el[(size_t)n * 4 + z];
            v = (bag[g * 4 + z] > 0.f) ? v : -1e9f;
            lz[z] = v; m4 = fmaxf(m4, v);
        }
        float s4 = 0.f;
#pragma unroll
        for (int z = 0; z < 4; z++) { lz[z] = expf(lz[z] - m4); s4 += lz[z]; }
#pragma unroll
        for (int z = 0; z < 4; z++) {
            lz[z] /= s4;
            hel -= lz[z] * logf(fmaxf(lz[z], 1e-20f));
        }
        pzel = lz[zel];
    }
    const float hef = wsum(fp * hel);
    const float lp = wsum((valid && lane == foc)
                          ? (logf(fp + 1e-20f) + logf(pzel + 1e-20f)) : 0.f);
    if (lane == 0) { g_lp12[g] = lp; out[2 * g + 1] = hfocus + hef; }
}

// ---------------- K5: distance MLP/GMM + cond + orientation logZ ----------------
__global__ void __launch_bounds__(128) k5_final(
    const int* __restrict__ ptr, const int* __restrict__ focus,
    const int* __restrict__ element, const float* __restrict__ distance,
    const float* __restrict__ orientation, const float* __restrict__ W_mix,
    const float* __restrict__ W1d, const float* __restrict__ b1d,
    const float* __restrict__ W2d, const float* __restrict__ b2d,
    const float* __restrict__ d_log_stds, float* __restrict__ out)
{
    const int tid = threadIdx.x, lane = tid & 31, wq = tid >> 5;
    const int gbase = blockIdx.x * 4;
    __shared__ float sSI[4][384];
    __shared__ int   sGI[4], sEl[4];
    __shared__ float sRed[4][4][6];
    if (tid < 4) {
        const int g = gbase + tid;
        sGI[tid] = (g < GG_) ? (ptr[g] + focus[g]) : 0;
        sEl[tid] = (g < GG_) ? element[g] : 0;
    }
    __syncthreads();
#pragma unroll
    for (int q = 0; q < 4; q++)
        for (int k = tid; k < 384; k += 128)
            sSI[q][k] = g_sinv[(size_t)sGI[q] * 384 + k];
    __syncthreads();

    float acc[4];
    const float b1 = b1d[tid];
#pragma unroll
    for (int q = 0; q < 4; q++) acc[q] = b1;
    for (int k = 0; k < 384; k++) {
        const float w = W1d[k * 128 + tid];
#pragma unroll
        for (int q = 0; q < 4; q++) acc[q] = fmaf(w, sSI[q][k], acc[q]);
    }
#pragma unroll
    for (int q = 0; q < 4; q++) acc[q] += W1d[(384 + sEl[q]) * 128 + tid];

    float w2[6];
#pragma unroll
    for (int j = 0; j < 6; j++) w2[j] = W2d[tid * 6 + j];
#pragma unroll
    for (int q = 0; q < 4; q++) {
        const float h = fmaxf(acc[q], 0.f);
        float v[6];
#pragma unroll
        for (int j = 0; j < 6; j++) v[j] = h * w2[j];
#pragma unroll
        for (int s = 16; s > 0; s >>= 1)
#pragma unroll
            for (int j = 0; j < 6; j++) v[j] += __shfl_down_sync(0xffffffffu, v[j], s);
        if (lane == 0)
#pragma unroll
            for (int j = 0; j < 6; j++) sRed[wq][q][j] = v[j];
    }
    __syncthreads();

    const int g = gbase + wq;
    if (g >= GG_) return;
    float hj[6];
#pragma unroll
    for (int j = 0; j < 6; j++)
        hj[j] = sRed[0][wq][j] + sRed[1][wq][j] + sRed[2][wq][j] + sRed[3][wq][j] + b2d[j];

    const float d = distance[g];
    float lm = fmaxf(hj[0], fmaxf(hj[1], hj[2]));
    float se = expf(hj[0] - lm) + expf(hj[1] - lm) + expf(hj[2] - lm);
    const float lse = lm + logf(se);
    float aj[3];
#pragma unroll
    for (int j = 0; j < 3; j++) {
        const float mean = tanhf(hj[3 + j]) * 0.45f + 1.35f;
        const float std  = fmaxf(expf(d_log_stds[j]), 1e-6f);
        const float t = (d - mean) / std;
        aj[j] = (hj[j] - lse) - 0.5f * t * t - logf(std) - 0.91893853320467274f;
    }
    float am = fmaxf(aj[0], fmaxf(aj[1], aj[2]));
    const float lp_dist = am + logf(expf(aj[0] - am) + expf(aj[1] - am) + expf(aj[2] - am));

    float bess[8];
#pragma unroll
    for (int k = 0; k < 8; k++)
        bess[k] = 1.0540925533894598f * sinf((float)(k + 1) * 3.14159265358979f * d / 1.8f) / d;

    const int zel = sEl[wq];
    float cond[9];
#pragma unroll
    for (int j = 0; j < 9; j++) cond[j] = 0.f;
    const float* scov = g_scov + (size_t)g * 1152;
#pragma unroll
    for (int ib = 0; ib < 4; ib++) {
        const int i = lane + ib * 32;
        {
            float tw = 0.f;
#pragma unroll
            for (int k = 0; k < 8; k++)
                tw = fmaf(bess[k], W_mix[k * 1536 + 0 * 512 + i * 4 + zel], tw);
            tw *= 0.3535533905932738f;
            cond[0] = fmaf(scov[i], tw, cond[0]);
        }
        {
            float tw = 0.f;
#pragma unroll
            for (int k = 0; k < 8; k++)
                tw = fmaf(bess[k], W_mix[k * 1536 + 1 * 512 + i * 4 + zel], tw);
            tw *= 0.3535533905932738f;
#pragma unroll
            for (int m = 0; m < 3; m++)
                cond[1 + m] = fmaf(scov[128 + i * 3 + m], tw, cond[1 + m]);
        }
        {
            float tw = 0.f;
#pragma unroll
            for (int k = 0; k < 8; k++)
                tw = fmaf(bess[k], W_mix[k * 1536 + 2 * 512 + i * 4 + zel], tw);
            tw *= 0.3535533905932738f;
#pragma unroll
            for (int m = 0; m < 5; m++)
                cond[4 + m] = fmaf(scov[512 + i * 5 + m], tw, cond[4 + m]);
        }
    }
#pragma unroll
    for (int j = 0; j < 9; j++) cond[j] = wsum(cond[j]) * INV_SQMZ;

    float m_run = -3.0e38f, s_run = 0.f;
    for (int t = 0; t < 128; t++) {
        const int p = lane + 32 * t;
        float f = 0.f;
#pragma unroll
        for (int j = 0; j < 9; j++) f = fmaf(cond[j], g_Y[j * PGRID + p], f);
        f *= 10.0f;
        const float nm = fmaxf(m_run, f);
        s_run = s_run * __expf(m_run - nm) + __expf(f - nm);
        m_run = nm;
    }
#pragma unroll
    for (int s = 16; s > 0; s >>= 1) {
        const float om = __shfl_xor_sync(0xffffffffu, m_run, s);
        const float os = __shfl_xor_sync(0xffffffffu, s_run, s);
        const float nm = fmaxf(m_run, om);
        s_run = s_run * __expf(m_run - nm) + os * __expf(om - nm);
        m_run = nm;
    }
    const float logZ = m_run + logf(s_run) - 8.317766166719343f + 2.5310242469692907f;

    if (lane == 0) {
        float ox = orientation[g * 3 + 0], oy = orientation[g * 3 + 1],
              oz = orientation[g * 3 + 2];
        const float inv = rsqrtf(ox * ox + oy * oy + oz * oz);
        ox *= inv; oy *= inv; oz *= inv;
        float sh[9];
        sh[0] = 0.28209479177387814f;
        sh[1] = 0.4886025119029199f * oy;
        sh[2] = 0.4886025119029199f * oz;
        sh[3] = 0.4886025119029199f * ox;
        sh[4] = 1.0925484305920792f * ox * oy;
        sh[5] = 1.0925484305920792f * oy * oz;
        sh[6] = 0.31539156525252005f * (3.f * oz * oz - 1.f);
        sh[7] = 1.0925484305920792f * ox * oz;
        sh[8] = 0.5462742152960396f * (ox * ox - oy * oy);
        float f_x = 0.f;
#pragma unroll
        for (int j = 0; j < 9; j++) f_x = fmaf(cond[j], sh[j], f_x);
        const float lp_ori = 10.0f * f_x - logZ;
        out[2 * g] = g_lp12[g] + lp_dist + lp_ori;
    }
}

// ---------------- launch ----------------
extern "C" void kernel_launch(void* const* d_in, const int* in_sizes, int n_in,
                              void* d_out, int out_size) {
    const float* s_inter     = (const float*)d_in[0];
    const float* bag         = (const float*)d_in[1];
    const int*   ptr         = (const int*)  d_in[3];
    const int*   focus       = (const int*)  d_in[4];
    const int*   element     = (const int*)  d_in[5];
    const float* distance    = (const float*)d_in[6];
    const float* orientation = (const float*)d_in[7];
    const float* W_bag       = (const float*)d_in[8];
    const float* d_log_stds  = (const float*)d_in[9];
    const float* W_mix       = (const float*)d_in[10];
    const float* W1f = (const float*)d_in[11];
    const float* b1f = (const float*)d_in[12];
    const float* W2f = (const float*)d_in[13];
    const float* b2f = (const float*)d_in[14];
    const float* W1e = (const float*)d_in[15];
    const float* b1e = (const float*)d_in[16];
    const float* W2e = (const float*)d_in[17];
    const float* b2e = (const float*)d_in[18];
    const float* W1d = (const float*)d_in[19];
    const float* b1d = (const float*)d_in[20];
    const float* W2d = (const float*)d_in[21];
    const float* b2d = (const float*)d_in[22];
    float* out = (float*)d_out;

    k0_ygrid<<<32, 128>>>();
    kW<<<GG_ * 3, 256>>>(W_bag, bag);
    k1_cov<2><<<GG_, 320>>>(s_inter, ptr, focus);
    k1_cov<1><<<GG_, 320>>>(s_inter, ptr, focus);
    k1_cov<0><<<GG_, 320>>>(s_inter, ptr, focus);
    k2_mlp<<<(NN_ + 31) / 32, 128>>>(W1f, b1f, W2f, b2f, W1e, b1e, W2e, b2e);
    k3_group<<<(GG_ + 3) / 4, 128>>>(bag, ptr, focus, element, out);
    k5_final<<<(GG_ + 3) / 4, 128>>>(ptr, focus, element, distance, orientation,
                                     W_mix, W1d, b1d, W2d, b2d, d_log_stds, out);
}